// round 1
// baseline (speedup 1.0000x reference)
#include <cuda_runtime.h>

#define B    100
#define DIN  2048
#define DH   1024
#define DOUT 1000

// Scratch (allocation-free rule: __device__ globals)
__device__ float d_hacc[B * DH];    // x@W1 partials + sum_i b1
__device__ float d_oacc[B * DOUT];  // h@W2 partials + sum_i b2
__device__ float d_h[B * DH];       // relu'd hidden

// ---------------------------------------------------------------------------
__global__ void zero_kernel() {
    int i = blockIdx.x * 256 + threadIdx.x;
    if (i < B * DH)   d_hacc[i] = 0.f;
    if (i < B * DOUT) d_oacc[i] = 0.f;
}

// Sum b1 over axis 1 (2048 rows) into d_hacc. Grid: (16 chunks, 100 batches).
// 256 threads * float4 = 1024 floats = one full row -> perfectly coalesced.
__global__ void reduce_b1_kernel(const float* __restrict__ b1) {
    const int b = blockIdx.y;
    const long long base = (long long)b * DIN * DH +
                           (long long)blockIdx.x * 128 * DH + threadIdx.x * 4;
    const float4* p = (const float4*)(b1 + base);
    float4 s = make_float4(0.f, 0.f, 0.f, 0.f);
#pragma unroll 8
    for (int i = 0; i < 128; ++i) {
        float4 v = p[(long long)i * (DH / 4)];
        s.x += v.x; s.y += v.y; s.z += v.z; s.w += v.w;
    }
    float* o = d_hacc + b * DH + threadIdx.x * 4;
    atomicAdd(o + 0, s.x); atomicAdd(o + 1, s.y);
    atomicAdd(o + 2, s.z); atomicAdd(o + 3, s.w);
}

// Sum b2 over axis 1 (1024 rows) into d_oacc. Grid: (8 chunks, 100 batches).
// 250 active threads * float4 = 1000 floats = one row (16B aligned: 1000=4*250).
__global__ void reduce_b2_kernel(const float* __restrict__ b2) {
    const int j4 = threadIdx.x;
    if (j4 >= DOUT / 4) return;
    const int b = blockIdx.y;
    const long long base = (long long)b * DH * DOUT +
                           (long long)blockIdx.x * 128 * DOUT + j4 * 4;
    const float4* p = (const float4*)(b2 + base);
    float4 s = make_float4(0.f, 0.f, 0.f, 0.f);
#pragma unroll 8
    for (int i = 0; i < 128; ++i) {
        float4 v = p[(long long)i * (DOUT / 4)];
        s.x += v.x; s.y += v.y; s.z += v.z; s.w += v.w;
    }
    float* o = d_oacc + b * DOUT + j4 * 4;
    atomicAdd(o + 0, s.x); atomicAdd(o + 1, s.y);
    atomicAdd(o + 2, s.z); atomicAdd(o + 3, s.w);
}

// k-split SGEMM accumulating into a __device__ scratch via atomicAdd.
// Block: 256 threads, tile 64 N-cols x all 100 M-rows, K-chunk = KC.
// Thread owns 4 consecutive n (float4 from ws) x 7 m  (16 strips * 7 = 112 >= 100).
// which==0: A=x (param), acc=d_hacc ; which==1: A=d_h, acc=d_oacc.
__global__ void gemm_acc_kernel(const float* __restrict__ Ain,
                                const float* __restrict__ Wm,
                                int K, int KC, int N, int ldacc, int which) {
    __shared__ float xs[112][33];   // pad 33: strips 7 rows apart land on distinct banks
    __shared__ float ws[32][64];

    const float* A = which ? d_h : Ain;
    float* acc     = which ? d_oacc : d_hacc;

    const int tid  = threadIdx.x;
    const int n0   = blockIdx.x * 64;
    const int k0   = blockIdx.y * KC;
    const int nl4  = tid & 15;       // 0..15 -> 4 n's each
    const int m0   = (tid >> 4) * 7; // strip * 7

    float r[7][4];
#pragma unroll
    for (int i = 0; i < 7; ++i)
#pragma unroll
        for (int j = 0; j < 4; ++j) r[i][j] = 0.f;

    for (int kb = k0; kb < k0 + KC; kb += 32) {
        for (int idx = tid; idx < 112 * 32; idx += 256) {
            int m = idx >> 5, kk = idx & 31;
            xs[m][kk] = (m < B) ? A[(long long)m * K + kb + kk] : 0.f;
        }
        for (int idx = tid; idx < 32 * 64; idx += 256) {
            int kk = idx >> 6, nn = idx & 63;
            int nc = n0 + nn;
            ws[kk][nn] = (nc < N) ? Wm[(long long)(kb + kk) * N + nc] : 0.f;
        }
        __syncthreads();
#pragma unroll
        for (int kk = 0; kk < 32; ++kk) {
            float4 wv = *(const float4*)&ws[kk][nl4 * 4];
#pragma unroll
            for (int mi = 0; mi < 7; ++mi) {
                float xv = xs[m0 + mi][kk];
                r[mi][0] += xv * wv.x; r[mi][1] += xv * wv.y;
                r[mi][2] += xv * wv.z; r[mi][3] += xv * wv.w;
            }
        }
        __syncthreads();
    }

#pragma unroll
    for (int mi = 0; mi < 7; ++mi) {
        int m = m0 + mi;
        if (m < B) {
            int n = n0 + nl4 * 4;
#pragma unroll
            for (int j = 0; j < 4; ++j)
                if (n + j < N)
                    atomicAdd(&acc[(long long)m * ldacc + n + j], r[mi][j]);
        }
    }
}

__global__ void relu_kernel() {
    int i = blockIdx.x * 256 + threadIdx.x;
    if (i < B * DH) {
        float v = d_hacc[i] * (1.0f / DIN);
        d_h[i] = v > 0.f ? v : 0.f;
    }
}

__global__ void final_kernel(float* __restrict__ out) {
    int i = blockIdx.x * 256 + threadIdx.x;
    if (i < B * DOUT) out[i] = d_oacc[i] * (1.0f / DH);
}

// ---------------------------------------------------------------------------
extern "C" void kernel_launch(void* const* d_in, const int* in_sizes, int n_in,
                              void* d_out, int out_size) {
    const float* x  = (const float*)d_in[0];
    const float* W1 = (const float*)d_in[1];
    const float* b1 = (const float*)d_in[2];
    const float* W2 = (const float*)d_in[3];
    const float* b2 = (const float*)d_in[4];
    float* out = (float*)d_out;

    zero_kernel<<<(B * DH + 255) / 256, 256>>>();

    reduce_b1_kernel<<<dim3(DIN / 128, B), 256>>>(b1);   // 1600 blocks, 839 MB
    reduce_b2_kernel<<<dim3(DH / 128, B), 256>>>(b2);    //  800 blocks, 410 MB

    // GEMM1: x[100,2048] @ W1[2048,1024] -> d_hacc (+= bias sums already there)
    gemm_acc_kernel<<<dim3(DH / 64, 8), 256>>>(x, W1, DIN, DIN / 8, DH, DH, 0);

    relu_kernel<<<(B * DH + 255) / 256, 256>>>();

    // GEMM2: d_h[100,1024] @ W2[1024,1000] -> d_oacc
    gemm_acc_kernel<<<dim3((DOUT + 63) / 64, 8), 256>>>(nullptr, W2, DH, DH / 8, DOUT, DOUT, 1);

    final_kernel<<<(B * DOUT + 255) / 256, 256>>>(out);
}

// round 2
// speedup vs baseline: 1.3636x; 1.3636x over previous
#include <cuda_runtime.h>

#define B    100
#define DIN  2048
#define DH   1024
#define DOUT 1000

// Scratch (allocation-free rule: __device__ globals)
__device__ float d_hacc[B * DH];    // x@W1 partials + sum_i b1
__device__ float d_oacc[B * DOUT];  // h@W2 partials + sum_i b2
__device__ float d_h[B * DH];       // relu'd hidden

// Split of reduce_b2 batches between mega1 and mega2 (to overlap gemm2)
#define R2_SPLIT 84                  // batches [0,84) in mega1, [84,100) in mega2
#define G1_BLOCKS 256                // gemm1: 16 ntiles x 16 ksplits
#define R1_BLOCKS 1600               // reduce_b1: 16 chunks x 100 batches
#define R2A_BLOCKS (R2_SPLIT * 8)    // 672
#define R2B_BLOCKS ((B - R2_SPLIT) * 8) // 128
#define G2_BLOCKS 256                // gemm2: 16 ntiles x 16 ksplits

// ---------------------------------------------------------------------------
__global__ void zero_kernel() {
    int i = blockIdx.x * 256 + threadIdx.x;
    if (i < B * DH)   d_hacc[i] = 0.f;
    if (i < B * DOUT) d_oacc[i] = 0.f;
}

// ---------------------------------------------------------------------------
// SIMT GEMM tile: all 100 M-rows x 64 N-cols, K range [k0, k0+kc).
// 256 threads: thread owns 7 m x 4 n. Accumulates into acc via atomicAdd.
__device__ __forceinline__ void gemm_block(const float* __restrict__ A,
                                           const float* __restrict__ Wm,
                                           float* __restrict__ acc,
                                           int K, int N, int ldacc,
                                           int k0, int kc, int n0) {
    __shared__ float xs[112][33];   // pad 33: 7-row strips hit distinct banks
    __shared__ float ws[32][64];

    const int tid = threadIdx.x;
    const int nl4 = tid & 15;        // 16 lanes * 4 cols = 64
    const int m0  = (tid >> 4) * 7;  // 16 strips * 7 = 112 >= 100

    float r[7][4];
#pragma unroll
    for (int i = 0; i < 7; ++i)
#pragma unroll
        for (int j = 0; j < 4; ++j) r[i][j] = 0.f;

    for (int kb = k0; kb < k0 + kc; kb += 32) {
        for (int idx = tid; idx < 112 * 32; idx += 256) {
            int m = idx >> 5, kk = idx & 31;
            xs[m][kk] = (m < B) ? A[(long long)m * K + kb + kk] : 0.f;
        }
        for (int idx = tid; idx < 32 * 64; idx += 256) {
            int kk = idx >> 6, nn = idx & 63;
            int nc = n0 + nn;
            ws[kk][nn] = (nc < N) ? Wm[(long long)(kb + kk) * N + nc] : 0.f;
        }
        __syncthreads();
#pragma unroll
        for (int kk = 0; kk < 32; ++kk) {
            float4 wv = *(const float4*)&ws[kk][nl4 * 4];
#pragma unroll
            for (int mi = 0; mi < 7; ++mi) {
                float xv = xs[m0 + mi][kk];
                r[mi][0] += xv * wv.x; r[mi][1] += xv * wv.y;
                r[mi][2] += xv * wv.z; r[mi][3] += xv * wv.w;
            }
        }
        __syncthreads();
    }

#pragma unroll
    for (int mi = 0; mi < 7; ++mi) {
        int m = m0 + mi;
        if (m < B) {
            int n = n0 + nl4 * 4;
#pragma unroll
            for (int j = 0; j < 4; ++j)
                if (n + j < N)
                    atomicAdd(&acc[(long long)m * ldacc + n + j], r[mi][j]);
        }
    }
}

// ---------------------------------------------------------------------------
// Column-sum of a [rows x width] slab (128 rows) into acc row `b`.
// wq = width/4 quads per row; 256 threads cover up to 1024 floats/row.
__device__ __forceinline__ void reduce_block(const float* __restrict__ src,
                                             float* __restrict__ acc,
                                             int b, int chunk, int rows_total,
                                             int width) {
    const int wq = width >> 2;
    const int j4 = threadIdx.x;
    if (j4 >= wq) return;
    const long long base = (long long)b * rows_total * width +
                           (long long)chunk * 128 * width + j4 * 4;
    const float4* p = (const float4*)(src + base);
    float4 s = make_float4(0.f, 0.f, 0.f, 0.f);
#pragma unroll 8
    for (int i = 0; i < 128; ++i) {
        float4 v = p[(long long)i * wq];
        s.x += v.x; s.y += v.y; s.z += v.z; s.w += v.w;
    }
    float* o = acc + (long long)b * width + j4 * 4;
    atomicAdd(o + 0, s.x); atomicAdd(o + 1, s.y);
    atomicAdd(o + 2, s.z); atomicAdd(o + 3, s.w);
}

// ---------------------------------------------------------------------------
// mega1: gemm1 (256 blocks) + reduce_b1 (1600) + reduce_b2 batches [0,84) (672)
__global__ void mega1_kernel(const float* __restrict__ x,
                             const float* __restrict__ W1,
                             const float* __restrict__ b1,
                             const float* __restrict__ b2) {
    int bid = blockIdx.x;
    if (bid < G1_BLOCKS) {
        int nt = bid & 15, ks = bid >> 4;
        gemm_block(x, W1, d_hacc, DIN, DH, DH, ks * 128, 128, nt * 64);
    } else if (bid < G1_BLOCKS + R1_BLOCKS) {
        int r = bid - G1_BLOCKS;
        reduce_block(b1, d_hacc, r >> 4, r & 15, DIN, DH);
    } else {
        int r = bid - (G1_BLOCKS + R1_BLOCKS);
        reduce_block(b2, d_oacc, r >> 3, r & 7, DH, DOUT);
    }
}

__global__ void relu_kernel() {
    int i = blockIdx.x * 256 + threadIdx.x;
    if (i < B * DH) {
        float v = d_hacc[i] * (1.0f / DIN);
        d_h[i] = v > 0.f ? v : 0.f;
    }
}

// mega2: gemm2 (256 blocks) + reduce_b2 batches [84,100) (128 blocks)
__global__ void mega2_kernel(const float* __restrict__ W2,
                             const float* __restrict__ b2) {
    int bid = blockIdx.x;
    if (bid < G2_BLOCKS) {
        int nt = bid & 15, ks = bid >> 4;
        gemm_block(d_h, W2, d_oacc, DH, DOUT, DOUT, ks * 64, 64, nt * 64);
    } else {
        int r = bid - G2_BLOCKS;
        reduce_block(b2, d_oacc, R2_SPLIT + (r >> 3), r & 7, DH, DOUT);
    }
}

__global__ void final_kernel(float* __restrict__ out) {
    int i = blockIdx.x * 256 + threadIdx.x;
    if (i < B * DOUT) out[i] = d_oacc[i] * (1.0f / DH);
}

// ---------------------------------------------------------------------------
extern "C" void kernel_launch(void* const* d_in, const int* in_sizes, int n_in,
                              void* d_out, int out_size) {
    const float* x  = (const float*)d_in[0];
    const float* W1 = (const float*)d_in[1];
    const float* b1 = (const float*)d_in[2];
    const float* W2 = (const float*)d_in[3];
    const float* b2 = (const float*)d_in[4];
    float* out = (float*)d_out;

    zero_kernel<<<(B * DH + 255) / 256, 256>>>();

    mega1_kernel<<<G1_BLOCKS + R1_BLOCKS + R2A_BLOCKS, 256>>>(x, W1, b1, b2);

    relu_kernel<<<(B * DH + 255) / 256, 256>>>();

    mega2_kernel<<<G2_BLOCKS + R2B_BLOCKS, 256>>>(W2, b2);

    final_kernel<<<(B * DOUT + 255) / 256, 256>>>(out);
}

// round 3
// speedup vs baseline: 1.4023x; 1.0284x over previous
#include <cuda_runtime.h>

#define B    100
#define DIN  2048
#define DH   1024
#define DOUT 1000

__device__ float d_hacc[B * DH];    // relu-input accumulator (pre-scaled by 1/DIN)

#define G1_BLOCKS 256                // gemm1: 16 ntiles x 16 ksplits (kc=128)
#define R1_BLOCKS 1600               // reduce_b1: 100 batches x 16 chunks (128 rows)
#define G2_BLOCKS 256                // gemm2: 16 ntiles x 16 ksplits (kc=64)
#define R2_BLOCKS 1600               // reduce_b2: 100 batches x 16 chunks (64 rows)

// ---------------------------------------------------------------------------
__global__ void zero_kernel(float* __restrict__ out) {
    int i = blockIdx.x * 256 + threadIdx.x;
    if (i < B * DH)   d_hacc[i] = 0.f;
    if (i < B * DOUT) out[i] = 0.f;
}

// ---------------------------------------------------------------------------
// SIMT GEMM tile: all 100 M-rows x 64 N-cols, K range [k0, k0+kc).
// 256 threads: thread owns 7 m x 4 n. Accumulates scale*r into acc atomically.
// relu_in: apply max(v,0) to A elements on load (A already scaled upstream).
__device__ __forceinline__ void gemm_block(const float* __restrict__ A,
                                           const float* __restrict__ Wm,
                                           float* __restrict__ acc,
                                           int K, int N, int ldacc,
                                           int k0, int kc, int n0,
                                           float scale, bool relu_in) {
    __shared__ float xs[112][33];   // pad 33: 7-row strips hit distinct banks
    __shared__ float ws[32][64];

    const int tid = threadIdx.x;
    const int nl4 = tid & 15;        // 16 lanes * 4 cols = 64
    const int m0  = (tid >> 4) * 7;  // 16 strips * 7 = 112 >= 100

    float r[7][4];
#pragma unroll
    for (int i = 0; i < 7; ++i)
#pragma unroll
        for (int j = 0; j < 4; ++j) r[i][j] = 0.f;

    for (int kb = k0; kb < k0 + kc; kb += 32) {
        for (int idx = tid; idx < 112 * 32; idx += 256) {
            int m = idx >> 5, kk = idx & 31;
            float v = (m < B) ? A[(long long)m * K + kb + kk] : 0.f;
            if (relu_in) v = fmaxf(v, 0.f);
            xs[m][kk] = v;
        }
        for (int idx = tid; idx < 32 * 64; idx += 256) {
            int kk = idx >> 6, nn = idx & 63;
            int nc = n0 + nn;
            ws[kk][nn] = (nc < N) ? Wm[(long long)(kb + kk) * N + nc] : 0.f;
        }
        __syncthreads();
#pragma unroll
        for (int kk = 0; kk < 32; ++kk) {
            float4 wv = *(const float4*)&ws[kk][nl4 * 4];
#pragma unroll
            for (int mi = 0; mi < 7; ++mi) {
                float xv = xs[m0 + mi][kk];
                r[mi][0] += xv * wv.x; r[mi][1] += xv * wv.y;
                r[mi][2] += xv * wv.z; r[mi][3] += xv * wv.w;
            }
        }
        __syncthreads();
    }

#pragma unroll
    for (int mi = 0; mi < 7; ++mi) {
        int m = m0 + mi;
        if (m < B) {
            int n = n0 + nl4 * 4;
#pragma unroll
            for (int j = 0; j < 4; ++j)
                if (n + j < N)
                    atomicAdd(&acc[(long long)m * ldacc + n + j], r[mi][j] * scale);
        }
    }
}

// ---------------------------------------------------------------------------
// Column-sum of `rows` rows of a [rows_total x width] slab into acc row b,
// scaled. Coalesced float4 loads; up to width/4 threads active.
__device__ __forceinline__ void reduce_block(const float* __restrict__ src,
                                             float* __restrict__ acc,
                                             int b, int chunk, int rows,
                                             int rows_total, int width,
                                             float scale) {
    const int wq = width >> 2;
    const int j4 = threadIdx.x;
    if (j4 >= wq) return;
    const long long base = (long long)b * rows_total * width +
                           (long long)chunk * rows * width + j4 * 4;
    const float4* p = (const float4*)(src + base);
    float4 s = make_float4(0.f, 0.f, 0.f, 0.f);
#pragma unroll 8
    for (int i = 0; i < rows; ++i) {
        float4 v = p[(long long)i * wq];
        s.x += v.x; s.y += v.y; s.z += v.z; s.w += v.w;
    }
    float* o = acc + (long long)b * width + j4 * 4;
    atomicAdd(o + 0, s.x * scale); atomicAdd(o + 1, s.y * scale);
    atomicAdd(o + 2, s.z * scale); atomicAdd(o + 3, s.w * scale);
}

// ---------------------------------------------------------------------------
// mega1: gemm1 (256 blocks) + reduce_b1 (1600 blocks), both scaled by 1/DIN,
// accumulating into d_hacc. (relu deferred to mega2's load.)
__global__ void mega1_kernel(const float* __restrict__ x,
                             const float* __restrict__ W1,
                             const float* __restrict__ b1) {
    int bid = blockIdx.x;
    if (bid < G1_BLOCKS) {
        int nt = bid & 15, ks = bid >> 4;
        gemm_block(x, W1, d_hacc, DIN, DH, DH, ks * 128, 128, nt * 64,
                   1.0f / DIN, false);
    } else {
        int r = bid - G1_BLOCKS;
        reduce_block(b1, d_hacc, r >> 4, r & 15, 128, DIN, DH, 1.0f / DIN);
    }
}

// mega2: gemm2 (256 blocks, relu applied on A-load) + reduce_b2 (1600 blocks),
// both scaled by 1/DH, accumulating directly into out.
__global__ void mega2_kernel(const float* __restrict__ W2,
                             const float* __restrict__ b2,
                             float* __restrict__ out) {
    int bid = blockIdx.x;
    if (bid < G2_BLOCKS) {
        int nt = bid & 15, ks = bid >> 4;
        gemm_block(d_hacc, W2, out, DH, DOUT, DOUT, ks * 64, 64, nt * 64,
                   1.0f / DH, true);
    } else {
        int r = bid - G2_BLOCKS;
        reduce_block(b2, out, r >> 4, r & 15, 64, DH, DOUT, 1.0f / DH);
    }
}

// ---------------------------------------------------------------------------
extern "C" void kernel_launch(void* const* d_in, const int* in_sizes, int n_in,
                              void* d_out, int out_size) {
    const float* x  = (const float*)d_in[0];
    const float* W1 = (const float*)d_in[1];
    const float* b1 = (const float*)d_in[2];
    const float* W2 = (const float*)d_in[3];
    const float* b2 = (const float*)d_in[4];
    float* out = (float*)d_out;

    zero_kernel<<<(B * DH + 255) / 256, 256>>>(out);

    mega1_kernel<<<G1_BLOCKS + R1_BLOCKS, 256>>>(x, W1, b1);

    mega2_kernel<<<G2_BLOCKS + R2_BLOCKS, 256>>>(W2, b2, out);
}